// round 2
// baseline (speedup 1.0000x reference)
#include <cuda_runtime.h>
#include <cuda_bf16.h>
#include <mma.h>

using namespace nvcuda;

#define BATCH 64
#define CIN   512
#define PCH   256
#define COUT  1024
#define HW1   784   // 28*28
#define HW2   196   // 14*14

// ---------------- scratch (static device arrays; no runtime alloc) ----------
__device__ __nv_bfloat16 g_xq [BATCH * CIN  * HW1];   // quantized input (int values in bf16)
__device__ __nv_bfloat16 g_y1 [BATCH * PCH  * HW1];   // conv1 output, quantized ints
__device__ __nv_bfloat16 g_y2 [BATCH * PCH  * HW2];   // conv2 output, quantized ints
__device__ float         g_res[BATCH * COUT * HW2];   // shortcut branch (float)
__device__ __nv_bfloat16 g_w1q[PCH  * CIN];
__device__ __nv_bfloat16 g_w2q[PCH  * PCH * 9];
__device__ __nv_bfloat16 g_w3q[COUT * PCH];
__device__ __nv_bfloat16 g_wsq[COUT * CIN];
__device__ unsigned      g_maxbits[4];                // |w|max bit patterns: w1,w2,w3,ws

// ---------------- small kernels ---------------------------------------------
__global__ void reset_kernel() {
    if (threadIdx.x < 4) g_maxbits[threadIdx.x] = 0u;
}

__global__ void maxabs_kernel(const float* __restrict__ src, int n, int slot) {
    float m = 0.f;
    for (int i = blockIdx.x * blockDim.x + threadIdx.x; i < n; i += gridDim.x * blockDim.x)
        m = fmaxf(m, fabsf(src[i]));
    #pragma unroll
    for (int o = 16; o; o >>= 1) m = fmaxf(m, __shfl_xor_sync(0xffffffffu, m, o));
    __shared__ float sm[8];
    if ((threadIdx.x & 31) == 0) sm[threadIdx.x >> 5] = m;
    __syncthreads();
    if (threadIdx.x < 8) {
        m = sm[threadIdx.x];
        #pragma unroll
        for (int o = 4; o; o >>= 1) m = fmaxf(m, __shfl_xor_sync(0xffu, m, o));
        if (threadIdx.x == 0) atomicMax(&g_maxbits[slot], __float_as_uint(m));
    }
}

template <int SLOT>
__global__ void quantw_kernel(const float* __restrict__ src, int n) {
    __nv_bfloat16* dst = (SLOT == 0) ? g_w1q : (SLOT == 1) ? g_w2q : (SLOT == 2) ? g_w3q : g_wsq;
    const float s = __uint_as_float(g_maxbits[SLOT]);
    for (int i = blockIdx.x * blockDim.x + threadIdx.x; i < n; i += gridDim.x * blockDim.x) {
        float q = rintf(fminf(fmaxf(src[i] / s, -1.f), 1.f) * 127.f);
        dst[i] = __float2bfloat16(q);
    }
}

__global__ void quantx_kernel(const float* __restrict__ x) {
    const int n4 = BATCH * CIN * HW1 / 4;
    int i = blockIdx.x * blockDim.x + threadIdx.x;
    if (i >= n4) return;
    float4 v = reinterpret_cast<const float4*>(x)[i];
    __nv_bfloat16* d = g_xq + (size_t)i * 4;
    d[0] = __float2bfloat16(rintf(fminf(fmaxf(v.x * 2.f, -1.f), 1.f) * 127.f));
    d[1] = __float2bfloat16(rintf(fminf(fmaxf(v.y * 2.f, -1.f), 1.f) * 127.f));
    d[2] = __float2bfloat16(rintf(fminf(fmaxf(v.z * 2.f, -1.f), 1.f) * 127.f));
    d[3] = __float2bfloat16(rintf(fminf(fmaxf(v.w * 2.f, -1.f), 1.f) * 127.f));
}

// ---------------- tiled GEMM with fused conv epilogues ----------------------
// MODE 0: conv1 1x1    M=256,  K=512,  N=784  (B: g_xq contiguous)  -> g_y1
// MODE 1: conv2 3x3/s2 M=256,  K=2304, N=196  (B: gather from g_y1) -> g_y2
// MODE 2: shortcut s2  M=1024, K=512,  N=196  (B: strided g_xq)     -> g_res
// MODE 3: conv3 1x1    M=1024, K=256,  N=196  (B: g_y2) + residual  -> d_out
#define BM 128
#define BN 64
#define BK 32
#define LDA 40
#define LDB 72
#define LDC 72

template <int MODE>
__global__ __launch_bounds__(256) void gemm_kernel(const float* __restrict__ bias,
                                                   float* __restrict__ dout) {
    constexpr int M = (MODE <= 1) ? PCH : COUT;
    constexpr int K = (MODE == 0 || MODE == 2) ? CIN : (MODE == 1 ? PCH * 9 : PCH);
    constexpr int N = (MODE == 0) ? HW1 : HW2;

    const int tid = threadIdx.x;
    const int n0  = blockIdx.x * BN;
    const int m0  = blockIdx.y * BM;
    const int img = blockIdx.z;

    __shared__ __align__(128) unsigned char smem_raw[BM * LDC * 4];
    __nv_bfloat16* As = reinterpret_cast<__nv_bfloat16*>(smem_raw);
    __nv_bfloat16* Bs = As + BM * LDA;
    float*         Cs = reinterpret_cast<float*>(smem_raw);

    const __nv_bfloat16* Aw =
        (MODE == 0) ? g_w1q : (MODE == 1) ? g_w2q : (MODE == 2) ? g_wsq : g_w3q;

    wmma::fragment<wmma::accumulator, 16, 16, 16, float> c[2][2];
    #pragma unroll
    for (int i = 0; i < 2; i++)
        #pragma unroll
        for (int j = 0; j < 2; j++) wmma::fill_fragment(c[i][j], 0.f);

    const int warp = tid >> 5;
    const int wr = warp >> 1;   // 0..3 (M direction)
    const int wc = warp & 1;    // 0..1 (N direction)

    const int krow = tid >> 3;        // 0..31
    const int nc0  = (tid & 7) * 8;   // 0..56

    const __nv_bfloat16 bz = __float2bfloat16(0.f);

    for (int k0 = 0; k0 < K; k0 += BK) {
        // ---- load A tile (weights, row-major [BM x BK]) ----
        #pragma unroll
        for (int it = 0; it < 2; it++) {
            int idx = (tid + it * 256) * 8;
            int row = idx / BK, col = idx % BK;
            *reinterpret_cast<uint4*>(As + row * LDA + col) =
                *reinterpret_cast<const uint4*>(Aw + (size_t)(m0 + row) * K + k0 + col);
        }
        // ---- load B tile [BK x BN] ----
        {
            int gk = k0 + krow;
            __nv_bfloat16* db = Bs + krow * LDB + nc0;
            if (MODE == 0) {
                const __nv_bfloat16* src =
                    g_xq + (size_t)img * CIN * HW1 + (size_t)gk * HW1 + n0 + nc0;
                if (n0 + nc0 + 8 <= N) {
                    *reinterpret_cast<uint4*>(db) = *reinterpret_cast<const uint4*>(src);
                } else {
                    #pragma unroll
                    for (int j = 0; j < 8; j++) {
                        int gn = n0 + nc0 + j;
                        db[j] = (gn < N) ? src[j] : bz;
                    }
                }
            } else if (MODE == 3) {
                const __nv_bfloat16* src = g_y2 + (size_t)img * PCH * HW2 + (size_t)gk * HW2;
                #pragma unroll
                for (int j = 0; j < 8; j++) {
                    int gn = n0 + nc0 + j;
                    db[j] = (gn < N) ? src[gn] : bz;
                }
            } else if (MODE == 2) {
                const __nv_bfloat16* src = g_xq + (size_t)img * CIN * HW1 + (size_t)gk * HW1;
                #pragma unroll
                for (int j = 0; j < 8; j++) {
                    int gn = n0 + nc0 + j;
                    __nv_bfloat16 v = bz;
                    if (gn < N) {
                        int oh = gn / 14, ow = gn - oh * 14;
                        v = src[oh * 56 + ow * 2];   // stride-2 sample
                    }
                    db[j] = v;
                }
            } else {  // MODE == 1 : implicit 3x3 stride-2 pad-1 gather
                int ci = gk / 9;
                int rs = gk - ci * 9;
                int r = rs / 3, s = rs - r * 3;
                const __nv_bfloat16* src = g_y1 + (size_t)img * PCH * HW1 + (size_t)ci * HW1;
                #pragma unroll
                for (int j = 0; j < 8; j++) {
                    int gn = n0 + nc0 + j;
                    __nv_bfloat16 v = bz;
                    if (gn < N) {
                        int oh = gn / 14, ow = gn - oh * 14;
                        int ih = oh * 2 - 1 + r, iw = ow * 2 - 1 + s;
                        if ((unsigned)ih < 28u && (unsigned)iw < 28u) v = src[ih * 28 + iw];
                    }
                    db[j] = v;
                }
            }
        }
        __syncthreads();

        #pragma unroll
        for (int kk = 0; kk < 2; kk++) {
            wmma::fragment<wmma::matrix_a, 16, 16, 16, __nv_bfloat16, wmma::row_major> fa[2];
            wmma::fragment<wmma::matrix_b, 16, 16, 16, __nv_bfloat16, wmma::row_major> fb[2];
            wmma::load_matrix_sync(fa[0], As + (wr * 32) * LDA + kk * 16, LDA);
            wmma::load_matrix_sync(fa[1], As + (wr * 32 + 16) * LDA + kk * 16, LDA);
            wmma::load_matrix_sync(fb[0], Bs + (kk * 16) * LDB + wc * 32, LDB);
            wmma::load_matrix_sync(fb[1], Bs + (kk * 16) * LDB + wc * 32 + 16, LDB);
            #pragma unroll
            for (int i = 0; i < 2; i++)
                #pragma unroll
                for (int j = 0; j < 2; j++)
                    wmma::mma_sync(c[i][j], fa[i], fb[j], c[i][j]);
        }
        __syncthreads();
    }

    // ---- spill accumulators to smem for coalesced epilogue ----
    #pragma unroll
    for (int i = 0; i < 2; i++)
        #pragma unroll
        for (int j = 0; j < 2; j++)
            wmma::store_matrix_sync(Cs + (wr * 32 + i * 16) * LDC + wc * 32 + j * 16,
                                    c[i][j], LDC, wmma::mem_row_major);
    __syncthreads();

    float scaleW, c2s = 0.f;
    if (MODE == 0)      scaleW = __uint_as_float(g_maxbits[0]);
    else if (MODE == 1) scaleW = __uint_as_float(g_maxbits[1]);
    else if (MODE == 2) scaleW = __uint_as_float(g_maxbits[3]);
    else { scaleW = __uint_as_float(g_maxbits[2]); c2s = __uint_as_float(g_maxbits[1]); }

    constexpr float INVQ2 = 1.f / 16129.f;   // 1/127^2

    #pragma unroll 4
    for (int e = 0; e < BM * BN / 256; e++) {
        int idx = tid + e * 256;
        int m = idx >> 6, n = idx & 63;
        int gn = n0 + n;
        if (gn >= N) continue;
        int co = m0 + m;
        float acc = Cs[m * LDC + n];
        if (MODE == 0 || MODE == 1) {
            // out=(conv+qb/(cs*s0a))*cs ; relu6s*s ; fq_act  (s0=s1=s2a=0.5)
            float qb = rintf(bias[co] * 127.f) * (1.f / 127.f);
            float t  = acc * (scaleW * INVQ2) + qb * 2.f;
            float v  = fminf(fmaxf(t * 2.f, 0.f), 6.f) * 0.5f;
            float y  = rintf(fminf(fmaxf(v * 2.f, -1.f), 1.f) * 127.f);
            if (MODE == 0)
                g_y1[(size_t)img * PCH * HW1 + (size_t)co * HW1 + gn] = __float2bfloat16(y);
            else
                g_y2[(size_t)img * PCH * HW2 + (size_t)co * HW2 + gn] = __float2bfloat16(y);
        } else if (MODE == 2) {
            // residual = convS*css*s0 + qbs
            float qb = rintf(bias[co] * 127.f) * (1.f / 127.f);
            g_res[(size_t)img * COUT * HW2 + (size_t)co * HW2 + gn] =
                acc * (scaleW * 0.5f * INVQ2) + qb;
        } else {
            // main = conv3*c3s*s2a + qb3*c3s/c2s ; out = clip(main+res, 0, 6)
            float qb3   = rintf(bias[co] * 127.f) * (1.f / 127.f);
            float mainv = acc * (scaleW * 0.5f * INVQ2) + qb3 * (scaleW / c2s);
            size_t off  = (size_t)img * COUT * HW2 + (size_t)co * HW2 + gn;
            dout[off]   = fminf(fmaxf(mainv + g_res[off], 0.f), 6.f);
        }
    }
}

// ---------------- launch ------------------------------------------------------
extern "C" void kernel_launch(void* const* d_in, const int* in_sizes, int n_in,
                              void* d_out, int out_size) {
    const float* x  = (const float*)d_in[0];
    const float* w1 = (const float*)d_in[1];
    const float* b1 = (const float*)d_in[2];
    const float* w2 = (const float*)d_in[3];
    const float* b2 = (const float*)d_in[4];
    const float* w3 = (const float*)d_in[5];
    const float* b3 = (const float*)d_in[6];
    const float* ws = (const float*)d_in[7];
    const float* bs = (const float*)d_in[8];
    float* out = (float*)d_out;

    reset_kernel<<<1, 32>>>();

    maxabs_kernel<<<128, 256>>>(w1, PCH * CIN, 0);
    maxabs_kernel<<<256, 256>>>(w2, PCH * PCH * 9, 1);
    maxabs_kernel<<<128, 256>>>(w3, COUT * PCH, 2);
    maxabs_kernel<<<256, 256>>>(ws, COUT * CIN, 3);

    quantw_kernel<0><<<(PCH * CIN + 255) / 256, 256>>>(w1, PCH * CIN);
    quantw_kernel<1><<<(PCH * PCH * 9 + 255) / 256, 256>>>(w2, PCH * PCH * 9);
    quantw_kernel<2><<<(COUT * PCH + 255) / 256, 256>>>(w3, COUT * PCH);
    quantw_kernel<3><<<(COUT * CIN + 255) / 256, 256>>>(ws, COUT * CIN);

    {
        int n4 = BATCH * CIN * HW1 / 4;
        quantx_kernel<<<(n4 + 255) / 256, 256>>>(x);
    }

    // conv1: M=256, N=784
    gemm_kernel<0><<<dim3((HW1 + BN - 1) / BN, PCH / BM, BATCH), 256>>>(b1, nullptr);
    // conv2: M=256, N=196
    gemm_kernel<1><<<dim3((HW2 + BN - 1) / BN, PCH / BM, BATCH), 256>>>(b2, nullptr);
    // shortcut: M=1024, N=196
    gemm_kernel<2><<<dim3((HW2 + BN - 1) / BN, COUT / BM, BATCH), 256>>>(bs, nullptr);
    // conv3 + residual + final relu6: M=1024, N=196
    gemm_kernel<3><<<dim3((HW2 + BN - 1) / BN, COUT / BM, BATCH), 256>>>(b3, out);
}

// round 3
// speedup vs baseline: 1.8242x; 1.8242x over previous
#include <cuda_runtime.h>
#include <cuda_bf16.h>
#include <mma.h>

using namespace nvcuda;

#define BATCH 64
#define CIN   512
#define PCH   256
#define COUT  1024
#define HW1   784   // 28*28
#define HW2   196   // 14*14
#define N1    (BATCH * HW1)   // 50176 (conv1 flattened N)
#define N2    (BATCH * HW2)   // 12544 (conv2/3/shortcut flattened N)
#define K2    (PCH * 9)       // 2304

// ---------------- scratch (static device arrays; no runtime alloc) ----------
__device__ __nv_bfloat16 g_xq [BATCH * CIN * HW1];   // quantized input ints (bf16)
__device__ __nv_bfloat16 g_xs [BATCH * CIN * HW2];   // stride-2 downsampled xq
__device__ __nv_bfloat16 g_y1 [BATCH * PCH * HW1];   // conv1 out, quantized ints
__device__ __nv_bfloat16 g_im2[K2 * N2];             // im2col of g_y1 for conv2
__device__ __nv_bfloat16 g_y2 [BATCH * PCH * HW2];   // conv2 out, quantized ints
__device__ __nv_bfloat16 g_w1q[PCH  * CIN];
__device__ __nv_bfloat16 g_w2q[PCH  * K2];
__device__ __nv_bfloat16 g_w3q[COUT * PCH];
__device__ __nv_bfloat16 g_wsq[COUT * CIN];
__device__ unsigned      g_maxbits[4];               // |w|max bits: w1,w2,w3,ws

// ---------------- cp.async helpers ------------------------------------------
__device__ __forceinline__ void cp16(void* s, const void* g) {
    unsigned sa = (unsigned)__cvta_generic_to_shared(s);
    asm volatile("cp.async.cg.shared.global [%0],[%1],16;\n" :: "r"(sa), "l"(g));
}
__device__ __forceinline__ void cp8(void* s, const void* g) {
    unsigned sa = (unsigned)__cvta_generic_to_shared(s);
    asm volatile("cp.async.ca.shared.global [%0],[%1],8;\n" :: "r"(sa), "l"(g));
}
#define CP_COMMIT asm volatile("cp.async.commit_group;\n" ::: "memory")
#define CP_WAIT1  asm volatile("cp.async.wait_group 1;\n" ::: "memory")

// ---------------- setup kernels ---------------------------------------------
__global__ void reset_kernel() {
    if (threadIdx.x < 4) g_maxbits[threadIdx.x] = 0u;
}

__global__ void maxabs_all(const float* __restrict__ w1, const float* __restrict__ w2,
                           const float* __restrict__ w3, const float* __restrict__ ws) {
    int slot = blockIdx.y;
    const float* src = slot == 0 ? w1 : slot == 1 ? w2 : slot == 2 ? w3 : ws;
    int n4 = (slot == 0 ? PCH * CIN : slot == 1 ? PCH * K2 : slot == 2 ? COUT * PCH : COUT * CIN) / 4;
    float m = 0.f;
    for (int i = blockIdx.x * blockDim.x + threadIdx.x; i < n4; i += gridDim.x * blockDim.x) {
        float4 v = reinterpret_cast<const float4*>(src)[i];
        m = fmaxf(m, fmaxf(fmaxf(fabsf(v.x), fabsf(v.y)), fmaxf(fabsf(v.z), fabsf(v.w))));
    }
    #pragma unroll
    for (int o = 16; o; o >>= 1) m = fmaxf(m, __shfl_xor_sync(0xffffffffu, m, o));
    __shared__ float sm[8];
    if ((threadIdx.x & 31) == 0) sm[threadIdx.x >> 5] = m;
    __syncthreads();
    if (threadIdx.x < 8) {
        m = sm[threadIdx.x];
        #pragma unroll
        for (int o = 4; o; o >>= 1) m = fmaxf(m, __shfl_xor_sync(0xffu, m, o));
        if (threadIdx.x == 0) atomicMax(&g_maxbits[slot], __float_as_uint(m));
    }
}

__global__ void quantw_all(const float* __restrict__ w1, const float* __restrict__ w2,
                           const float* __restrict__ w3, const float* __restrict__ ws) {
    int slot = blockIdx.y;
    const float* src = slot == 0 ? w1 : slot == 1 ? w2 : slot == 2 ? w3 : ws;
    __nv_bfloat16* dst = slot == 0 ? g_w1q : slot == 1 ? g_w2q : slot == 2 ? g_w3q : g_wsq;
    int n4 = (slot == 0 ? PCH * CIN : slot == 1 ? PCH * K2 : slot == 2 ? COUT * PCH : COUT * CIN) / 4;
    const float inv = 1.f / __uint_as_float(g_maxbits[slot]);
    for (int i = blockIdx.x * blockDim.x + threadIdx.x; i < n4; i += gridDim.x * blockDim.x) {
        float4 v = reinterpret_cast<const float4*>(src)[i];
        __nv_bfloat16 q[4];
        q[0] = __float2bfloat16(rintf(fminf(fmaxf(v.x * inv, -1.f), 1.f) * 127.f));
        q[1] = __float2bfloat16(rintf(fminf(fmaxf(v.y * inv, -1.f), 1.f) * 127.f));
        q[2] = __float2bfloat16(rintf(fminf(fmaxf(v.z * inv, -1.f), 1.f) * 127.f));
        q[3] = __float2bfloat16(rintf(fminf(fmaxf(v.w * inv, -1.f), 1.f) * 127.f));
        *reinterpret_cast<uint2*>(dst + (size_t)i * 4) = *reinterpret_cast<uint2*>(q);
    }
}

// quantize x AND emit the stride-2 downsampled copy for the shortcut branch
__global__ void quantx_ds(const float* __restrict__ x) {
    int i = blockIdx.x * blockDim.x + threadIdx.x;
    if (i >= BATCH * CIN * HW1 / 4) return;
    float4 v = reinterpret_cast<const float4*>(x)[i];
    __nv_bfloat16 q[4];
    q[0] = __float2bfloat16(rintf(fminf(fmaxf(v.x * 2.f, -1.f), 1.f) * 127.f));
    q[1] = __float2bfloat16(rintf(fminf(fmaxf(v.y * 2.f, -1.f), 1.f) * 127.f));
    q[2] = __float2bfloat16(rintf(fminf(fmaxf(v.z * 2.f, -1.f), 1.f) * 127.f));
    q[3] = __float2bfloat16(rintf(fminf(fmaxf(v.w * 2.f, -1.f), 1.f) * 127.f));
    *reinterpret_cast<uint2*>(g_xq + (size_t)i * 4) = *reinterpret_cast<uint2*>(q);
    int flat = i * 4;
    int o = flat % HW1;              // offset within one (img,channel) plane
    int h = o / 28, w0 = o - h * 28; // w0 % 4 == 0
    if ((h & 1) == 0) {
        __nv_bfloat16 d[2] = {q[0], q[2]};   // even-w samples
        *reinterpret_cast<unsigned*>(g_xs + (size_t)(flat / HW1) * HW2 +
                                     (h >> 1) * 14 + (w0 >> 1)) = *reinterpret_cast<unsigned*>(d);
    }
}

// im2col of g_y1 for conv2 (3x3, stride 2, pad 1): g_im2[c*9+rs][img*196+pix]
__global__ void im2col_kernel() {
    int idx = blockIdx.x * blockDim.x + threadIdx.x;
    if (idx >= K2 * (N2 / 4)) return;
    int row = idx / (N2 / 4);
    int gn0 = (idx - row * (N2 / 4)) * 4;
    int img = gn0 / HW2;
    int pix0 = gn0 - img * HW2;
    int c = row / 9, rs = row - c * 9;
    int r = rs / 3, s = rs - r * 3;
    const __nv_bfloat16* src = g_y1 + ((size_t)img * PCH + c) * HW1;
    __nv_bfloat16 v[4];
    #pragma unroll
    for (int j = 0; j < 4; j++) {
        int pix = pix0 + j;
        int oh = pix / 14, ow = pix - oh * 14;
        int ih = 2 * oh - 1 + r, iw = 2 * ow - 1 + s;
        v[j] = ((unsigned)ih < 28u && (unsigned)iw < 28u) ? src[ih * 28 + iw]
                                                          : __float2bfloat16(0.f);
    }
    *reinterpret_cast<uint2*>(g_im2 + (size_t)row * N2 + gn0) = *reinterpret_cast<uint2*>(v);
}

// ---------------- big GEMMs: conv1 (MODE 0) and conv2 (MODE 1) --------------
// C[M=256, N] = W[M,K] x Act[K,N], BM=128 BN=128 BK=32, 2-stage cp.async.
// Epilogue: bias + relu6s + fq_act, writes quantized ints (bf16).
template <int MODE>
__global__ __launch_bounds__(256) void gemm_big(const float* __restrict__ bias) {
    constexpr int K  = (MODE == 0) ? CIN : K2;
    constexpr int KT = K / 32;

    __shared__ __align__(16) unsigned char raw[37888];
    __nv_bfloat16* As = reinterpret_cast<__nv_bfloat16*>(raw);            // [2][128*40]
    __nv_bfloat16* Bs = reinterpret_cast<__nv_bfloat16*>(raw + 20480);    // [2][32*136]
    float*         Cs = reinterpret_cast<float*>(raw);                    // [64][132]

    const __nv_bfloat16* Aw = (MODE == 0) ? g_w1q : g_w2q;
    const int tid = threadIdx.x;
    const int n0  = blockIdx.x * 128;
    const int m0  = blockIdx.y * 128;
    const int warp = tid >> 5, wr = warp >> 1, wc = warp & 1;

    wmma::fragment<wmma::accumulator, 16, 16, 16, float> c[2][4];
    #pragma unroll
    for (int i = 0; i < 2; i++)
        #pragma unroll
        for (int j = 0; j < 4; j++) wmma::fill_fragment(c[i][j], 0.f);

    auto loadAB = [&](int s, int k0) {
        #pragma unroll
        for (int it = 0; it < 2; it++) {
            int ch = tid + it * 256;
            int row = ch >> 2, col = (ch & 3) * 8;
            cp16(As + s * 5120 + row * 40 + col,
                 Aw + (size_t)(m0 + row) * K + k0 + col);
        }
        #pragma unroll
        for (int it = 0; it < 2; it++) {
            int ch = tid + it * 256;
            int row = ch >> 4, col = (ch & 15) * 8;
            int gk = k0 + row, gn = n0 + col;
            const __nv_bfloat16* gp;
            if (MODE == 0) {
                int img = gn / HW1;
                gp = g_xq + ((size_t)img * CIN + gk) * HW1 + (gn - img * HW1);
            } else {
                gp = g_im2 + (size_t)gk * N2 + gn;
            }
            cp16(Bs + s * 4352 + row * 136 + col, gp);
        }
    };

    loadAB(0, 0);
    CP_COMMIT;
    for (int kt = 0; kt < KT; kt++) {
        int cur = kt & 1;
        if (kt + 1 < KT) loadAB(cur ^ 1, (kt + 1) * 32);
        CP_COMMIT;
        CP_WAIT1;
        __syncthreads();
        #pragma unroll
        for (int kk = 0; kk < 2; kk++) {
            wmma::fragment<wmma::matrix_a, 16, 16, 16, __nv_bfloat16, wmma::row_major> fa[2];
            wmma::fragment<wmma::matrix_b, 16, 16, 16, __nv_bfloat16, wmma::row_major> fb[4];
            wmma::load_matrix_sync(fa[0], As + cur * 5120 + (wr * 32) * 40 + kk * 16, 40);
            wmma::load_matrix_sync(fa[1], As + cur * 5120 + (wr * 32 + 16) * 40 + kk * 16, 40);
            #pragma unroll
            for (int j = 0; j < 4; j++)
                wmma::load_matrix_sync(fb[j], Bs + cur * 4352 + (kk * 16) * 136 + wc * 64 + j * 16, 136);
            #pragma unroll
            for (int i = 0; i < 2; i++)
                #pragma unroll
                for (int j = 0; j < 4; j++)
                    wmma::mma_sync(c[i][j], fa[i], fb[j], c[i][j]);
        }
        __syncthreads();
    }

    // epilogue in 2 rounds of 64 rows (smem can't hold full 128x128 f32 tile)
    const float kmul = __uint_as_float(g_maxbits[MODE == 0 ? 0 : 1]) * (1.f / 16129.f);
    #pragma unroll
    for (int r = 0; r < 2; r++) {
        if ((wr >> 1) == r) {
            int lr = (wr & 1) * 32;
            #pragma unroll
            for (int i = 0; i < 2; i++)
                #pragma unroll
                for (int j = 0; j < 4; j++)
                    wmma::store_matrix_sync(Cs + (lr + i * 16) * 132 + wc * 64 + j * 16,
                                            c[i][j], 132, wmma::mem_row_major);
        }
        __syncthreads();
        #pragma unroll
        for (int e = 0; e < 32; e++) {
            int idx = tid + e * 256;          // 0..8191
            int lm = idx >> 7, n = idx & 127;
            int m = m0 + r * 64 + lm;
            int gn = n0 + n;
            float acc = Cs[lm * 132 + n];
            float qb = rintf(bias[m] * 127.f) * (1.f / 127.f);
            float t  = acc * kmul + qb * 2.f;
            float v  = fminf(fmaxf(t * 2.f, 0.f), 6.f) * 0.5f;
            float y  = rintf(fminf(fmaxf(v * 2.f, -1.f), 1.f) * 127.f);
            if (MODE == 0) {
                int img = gn / HW1;
                g_y1[((size_t)img * PCH + m) * HW1 + gn - img * HW1] = __float2bfloat16(y);
            } else {
                int img = gn / HW2;
                g_y2[((size_t)img * PCH + m) * HW2 + gn - img * HW2] = __float2bfloat16(y);
            }
        }
        __syncthreads();
    }
}

// ---------------- fused shortcut + conv3 + residual + final relu6 -----------
template <int KT, int CCH>
__device__ __forceinline__ void run_phase(
    const __nv_bfloat16* __restrict__ Aw, const __nv_bfloat16* __restrict__ Bbase,
    __nv_bfloat16* As, __nv_bfloat16* Bs,
    wmma::fragment<wmma::accumulator, 16, 16, 16, float> (&c)[2][2],
    int m0, int n0, int tid, int wr, int wc)
{
    constexpr int K = KT * 32;
    auto loadAB = [&](int s, int k0) {
        #pragma unroll
        for (int it = 0; it < 2; it++) {
            int ch = tid + it * 256;
            int row = ch >> 2, col = (ch & 3) * 8;
            cp16(As + s * 5120 + row * 40 + col,
                 Aw + (size_t)(m0 + row) * K + k0 + col);
        }
        #pragma unroll
        for (int it = 0; it < 2; it++) {
            int ch = tid + it * 256;
            int row = ch >> 4, col = (ch & 15) * 4;
            int gk = k0 + row, gn = n0 + col;
            int img = gn / HW2, pix = gn - img * HW2;
            cp8(Bs + s * 2304 + row * 72 + col,
                Bbase + ((size_t)img * CCH + gk) * HW2 + pix);
        }
    };
    loadAB(0, 0);
    CP_COMMIT;
    for (int kt = 0; kt < KT; kt++) {
        int cur = kt & 1;
        if (kt + 1 < KT) loadAB(cur ^ 1, (kt + 1) * 32);
        CP_COMMIT;
        CP_WAIT1;
        __syncthreads();
        #pragma unroll
        for (int kk = 0; kk < 2; kk++) {
            wmma::fragment<wmma::matrix_a, 16, 16, 16, __nv_bfloat16, wmma::row_major> fa[2];
            wmma::fragment<wmma::matrix_b, 16, 16, 16, __nv_bfloat16, wmma::row_major> fb[2];
            wmma::load_matrix_sync(fa[0], As + cur * 5120 + (wr * 32) * 40 + kk * 16, 40);
            wmma::load_matrix_sync(fa[1], As + cur * 5120 + (wr * 32 + 16) * 40 + kk * 16, 40);
            wmma::load_matrix_sync(fb[0], Bs + cur * 2304 + (kk * 16) * 72 + wc * 32, 72);
            wmma::load_matrix_sync(fb[1], Bs + cur * 2304 + (kk * 16) * 72 + wc * 32 + 16, 72);
            #pragma unroll
            for (int i = 0; i < 2; i++)
                #pragma unroll
                for (int j = 0; j < 2; j++)
                    wmma::mma_sync(c[i][j], fa[i], fb[j], c[i][j]);
        }
        __syncthreads();
    }
}

__global__ __launch_bounds__(256) void gemm_fused(const float* __restrict__ b3,
                                                  const float* __restrict__ bsc,
                                                  float* __restrict__ out) {
    __shared__ __align__(16) unsigned char raw[34816];
    __nv_bfloat16* As = reinterpret_cast<__nv_bfloat16*>(raw);           // [2][128*40]
    __nv_bfloat16* Bs = reinterpret_cast<__nv_bfloat16*>(raw + 20480);   // [2][32*72]
    float*         Cs = reinterpret_cast<float*>(raw);                   // [128][68]

    const int tid = threadIdx.x;
    const int n0  = blockIdx.x * 64;
    const int m0  = blockIdx.y * 128;
    const int warp = tid >> 5, wr = warp >> 1, wc = warp & 1;

    wmma::fragment<wmma::accumulator, 16, 16, 16, float> cS[2][2], c3[2][2];
    #pragma unroll
    for (int i = 0; i < 2; i++)
        #pragma unroll
        for (int j = 0; j < 2; j++) {
            wmma::fill_fragment(cS[i][j], 0.f);
            wmma::fill_fragment(c3[i][j], 0.f);
        }

    // phase 1: shortcut GEMM (K=512, B = downsampled xq)
    run_phase<16, CIN>(g_wsq, g_xs, As, Bs, cS, m0, n0, tid, wr, wc);
    // phase 2: conv3 GEMM (K=256, B = y2)
    run_phase<8, PCH>(g_w3q, g_y2, As, Bs, c3, m0, n0, tid, wr, wc);

    const float c2s = __uint_as_float(g_maxbits[1]);
    const float c3s = __uint_as_float(g_maxbits[2]);
    const float css = __uint_as_float(g_maxbits[3]);
    const float k3 = c3s * 0.5f * (1.f / 16129.f);
    const float kS = css * 0.5f * (1.f / 16129.f);
    const float bk3 = c3s / c2s;

    // combine both accumulators elementwise in registers (identical layouts)
    #pragma unroll
    for (int i = 0; i < 2; i++)
        #pragma unroll
        for (int j = 0; j < 2; j++) {
            #pragma unroll
            for (int t = 0; t < c3[i][j].num_elements; t++)
                c3[i][j].x[t] = c3[i][j].x[t] * k3 + cS[i][j].x[t] * kS;
            wmma::store_matrix_sync(Cs + (wr * 32 + i * 16) * 68 + wc * 32 + j * 16,
                                    c3[i][j], 68, wmma::mem_row_major);
        }
    __syncthreads();

    #pragma unroll
    for (int e = 0; e < 32; e++) {
        int idx = tid + e * 256;          // 0..8191
        int lm = idx >> 6, n = idx & 63;
        int m = m0 + lm;
        int gn = n0 + n;
        float v = Cs[lm * 68 + n]
                + rintf(b3[m]  * 127.f) * (1.f / 127.f) * bk3
                + rintf(bsc[m] * 127.f) * (1.f / 127.f);
        int img = gn / HW2, pix = gn - img * HW2;
        out[((size_t)img * COUT + m) * HW2 + pix] = fminf(fmaxf(v, 0.f), 6.f);
    }
}

// ---------------- launch ------------------------------------------------------
extern "C" void kernel_launch(void* const* d_in, const int* in_sizes, int n_in,
                              void* d_out, int out_size) {
    const float* x  = (const float*)d_in[0];
    const float* w1 = (const float*)d_in[1];
    const float* b1 = (const float*)d_in[2];
    const float* w2 = (const float*)d_in[3];
    const float* b2 = (const float*)d_in[4];
    const float* w3 = (const float*)d_in[5];
    const float* b3 = (const float*)d_in[6];
    const float* ws = (const float*)d_in[7];
    const float* bs = (const float*)d_in[8];
    float* out = (float*)d_out;

    reset_kernel<<<1, 32>>>();
    maxabs_all<<<dim3(64, 4), 256>>>(w1, w2, w3, ws);
    quantw_all<<<dim3(160, 4), 256>>>(w1, w2, w3, ws);
    quantx_ds<<<(BATCH * CIN * HW1 / 4 + 255) / 256, 256>>>(x);

    // conv1: M=256, N=50176
    gemm_big<0><<<dim3(N1 / 128, 2), 256>>>(b1);
    // im2col for conv2
    im2col_kernel<<<(K2 * (N2 / 4) + 255) / 256, 256>>>();
    // conv2: M=256, N=12544
    gemm_big<1><<<dim3(N2 / 128, 2), 256>>>(b2);
    // shortcut + conv3 + residual + relu6: M=1024, N=12544
    gemm_fused<<<dim3(N2 / 64, 8), 256>>>(b3, bs, out);
}